// round 1
// baseline (speedup 1.0000x reference)
#include <cuda_runtime.h>
#include <math.h>

// Problem constants (fixed by the dataset)
#define D_DIM 1024
#define H_DIM 4096
#define E_NUM 8
#define MAXA  16384      // 2 * N assignments worst case (= exactly 2N here)

// GEMM tiling
#define BM 128
#define BN 128
#define BK 8
#define PAD 4

// ---------------- device scratch (static; no allocation) ----------------
__device__ float g_H[(size_t)MAXA * H_DIM];   // 256 MB: gelu(x W1^T + b1) per assignment
__device__ float g_Y[(size_t)MAXA * D_DIM];   // 64 MB : weighted expert output per assignment
__device__ int   g_bucket[E_NUM * MAXA];      // assignment ids per expert
__device__ int   g_cnt[E_NUM];
__device__ float g_wts[MAXA];                 // softmax gate weight per assignment

__device__ __forceinline__ float gelu_exact(float v) {
    return 0.5f * v * (1.0f + erff(v * 0.70710678118654752f));
}

// ---------------- zero routing counters ----------------
__global__ void zero_kernel() {
    if (threadIdx.x < E_NUM) g_cnt[threadIdx.x] = 0;
}

// ---------------- gate: logits, top-2, softmax weights, routing ----------------
__global__ void gate_kernel(const float* __restrict__ x,
                            const float* __restrict__ Wg, int N) {
    int warp = (blockIdx.x * blockDim.x + threadIdx.x) >> 5;
    int lane = threadIdx.x & 31;
    if (warp >= N) return;
    const float* xr = x + (size_t)warp * D_DIM;
    float acc[E_NUM];
    #pragma unroll
    for (int e = 0; e < E_NUM; e++) acc[e] = 0.0f;
    for (int d = lane; d < D_DIM; d += 32) {
        float xv = xr[d];
        #pragma unroll
        for (int e = 0; e < E_NUM; e++) acc[e] += xv * Wg[e * D_DIM + d];
    }
    #pragma unroll
    for (int e = 0; e < E_NUM; e++) {
        #pragma unroll
        for (int o = 16; o > 0; o >>= 1)
            acc[e] += __shfl_xor_sync(0xffffffffu, acc[e], o);
    }
    if (lane == 0) {
        float m1 = -INFINITY, m2 = -INFINITY;
        int i1 = 0, i2 = 0;
        #pragma unroll
        for (int e = 0; e < E_NUM; e++) {
            float l = acc[e];
            if (l > m1)      { m2 = m1; i2 = i1; m1 = l; i1 = e; }
            else if (l > m2) { m2 = l; i2 = e; }
        }
        // softmax over [m1, m2] with m1 >= m2
        float e1 = expf(m2 - m1);
        float inv = 1.0f / (1.0f + e1);
        int a0 = warp * 2, a1 = warp * 2 + 1;
        g_wts[a0] = inv;
        g_wts[a1] = e1 * inv;
        int p0 = atomicAdd(&g_cnt[i1], 1);
        g_bucket[i1 * MAXA + p0] = a0;
        int p1 = atomicAdd(&g_cnt[i2], 1);
        g_bucket[i2 * MAXA + p1] = a1;
    }
}

// ---------------- gathered NT SGEMM ----------------
// GELU_EPI=true : A = x rows (token = a>>1), W = W1 (E,H,D), bias = b1, out = g_H (rows = a, width H)
// GELU_EPI=false: A = g_H rows (row = a),    W = W2 (E,D,H), bias = b2, out = g_Y (rows = a, width D), scaled by g_wts[a]
template <int KDIM, int NOUT, bool GELU_EPI>
__global__ __launch_bounds__(256, 2)
void moe_gemm_kernel(const float* __restrict__ x,
                     const float* __restrict__ W,
                     const float* __restrict__ bias) {
    int e = blockIdx.z;
    int cnt = g_cnt[e];
    int m0 = blockIdx.y * BM;
    if (m0 >= cnt) return;
    int n0 = blockIdx.x * BN;

    __shared__ float As[BK][BM + PAD];
    __shared__ float Bs[BK][BN + PAD];
    __shared__ int   aidx[BM];

    int tid = threadIdx.x;
    for (int i = tid; i < BM; i += 256) {
        int mi = m0 + i;
        aidx[i] = (mi < cnt) ? g_bucket[e * MAXA + mi] : -1;
    }
    __syncthreads();

    const float* Asrc = GELU_EPI ? x : (const float*)g_H;
    const float* Wb   = W + (size_t)e * NOUT * KDIM;

    // per-thread load coords: one float4 of A tile, one float4 of B tile
    int lr = tid >> 1;            // 0..127 (row in tile)
    int lc = (tid & 1) * 4;       // 0 or 4 (k offset)

    int a_lr = aidx[lr];
    bool valid = (a_lr >= 0);
    int arow = GELU_EPI ? (a_lr >> 1) : a_lr;
    if (!valid) arow = 0;
    const float* Ap = Asrc + (size_t)arow * KDIM + lc;
    const float* Bp = Wb + (size_t)(n0 + lr) * KDIM + lc;

    int tx = tid & 15;            // 0..15 -> 8 output cols each
    int ty = tid >> 4;            // 0..15 -> 8 output rows each
    int tx8 = tx * 8, ty8 = ty * 8;

    float acc[8][8];
    #pragma unroll
    for (int i = 0; i < 8; i++)
        #pragma unroll
        for (int j = 0; j < 8; j++) acc[i][j] = 0.0f;

    for (int k0 = 0; k0 < KDIM; k0 += BK) {
        float4 av = valid ? *(const float4*)(Ap + k0) : make_float4(0.f, 0.f, 0.f, 0.f);
        float4 bv = *(const float4*)(Bp + k0);
        As[lc + 0][lr] = av.x; As[lc + 1][lr] = av.y;
        As[lc + 2][lr] = av.z; As[lc + 3][lr] = av.w;
        Bs[lc + 0][lr] = bv.x; Bs[lc + 1][lr] = bv.y;
        Bs[lc + 2][lr] = bv.z; Bs[lc + 3][lr] = bv.w;
        __syncthreads();

        #pragma unroll
        for (int k = 0; k < BK; k++) {
            float4 a0 = *(const float4*)&As[k][ty8];
            float4 a1 = *(const float4*)&As[k][ty8 + 4];
            float4 b0 = *(const float4*)&Bs[k][tx8];
            float4 b1 = *(const float4*)&Bs[k][tx8 + 4];
            float ra[8] = {a0.x, a0.y, a0.z, a0.w, a1.x, a1.y, a1.z, a1.w};
            float rb[8] = {b0.x, b0.y, b0.z, b0.w, b1.x, b1.y, b1.z, b1.w};
            #pragma unroll
            for (int i = 0; i < 8; i++)
                #pragma unroll
                for (int j = 0; j < 8; j++)
                    acc[i][j] += ra[i] * rb[j];
        }
        __syncthreads();
    }

    // epilogue
    const float* be = bias + (size_t)e * NOUT;
    #pragma unroll
    for (int i = 0; i < 8; i++) {
        int a = aidx[ty8 + i];
        if (a < 0) continue;
        float w = GELU_EPI ? 1.0f : g_wts[a];
        float* orow = (GELU_EPI ? g_H : g_Y) + (size_t)a * NOUT + n0;
        #pragma unroll
        for (int j = 0; j < 8; j++) {
            int n = tx8 + j;
            float v = acc[i][j] + be[n0 + n];
            if (GELU_EPI) v = gelu_exact(v);
            else          v *= w;
            orow[n] = v;
        }
    }
}

// ---------------- combine the two weighted expert outputs per token ----------------
__global__ void combine_kernel(float* __restrict__ out, int N) {
    int i = blockIdx.x * blockDim.x + threadIdx.x;
    int total = N * (D_DIM / 4);
    if (i >= total) return;
    int n = i / (D_DIM / 4);
    int c = i - n * (D_DIM / 4);
    const float4* Y = (const float4*)g_Y;
    float4 a = Y[(size_t)(2 * n) * (D_DIM / 4) + c];
    float4 b = Y[(size_t)(2 * n + 1) * (D_DIM / 4) + c];
    ((float4*)out)[i] = make_float4(a.x + b.x, a.y + b.y, a.z + b.z, a.w + b.w);
}

// ---------------- launch ----------------
extern "C" void kernel_launch(void* const* d_in, const int* in_sizes, int n_in,
                              void* d_out, int out_size) {
    const float* x  = (const float*)d_in[0];
    const float* Wg = (const float*)d_in[1];
    const float* W1 = (const float*)d_in[2];
    const float* b1 = (const float*)d_in[3];
    const float* W2 = (const float*)d_in[4];
    const float* b2 = (const float*)d_in[5];
    float* out = (float*)d_out;
    int N = in_sizes[0] / D_DIM;   // 8192

    zero_kernel<<<1, 32>>>();
    gate_kernel<<<(N + 7) / 8, 256>>>(x, Wg, N);
    moe_gemm_kernel<D_DIM, H_DIM, true ><<<dim3(H_DIM / BN, MAXA / BM, E_NUM), 256>>>(x, W1, b1);
    moe_gemm_kernel<H_DIM, D_DIM, false><<<dim3(D_DIM / BN, MAXA / BM, E_NUM), 256>>>(x, W2, b2);
    combine_kernel<<<(N * (D_DIM / 4) + 255) / 256, 256>>>(out, N);
}

// round 3
// speedup vs baseline: 1.8728x; 1.8728x over previous
#include <cuda_runtime.h>
#include <math.h>
#include <cstdint>

// Problem constants
#define D_DIM 1024
#define H_DIM 4096
#define E_NUM 8
#define MAXA  16384

// GEMM tiling
#define BM 128
#define BN 128
#define BK 16          // K elems per pipeline chunk
#define LDA (BM + 8)   // smem row stride (floats): 136 ≡ 8 (mod 32) -> conflict-free

// ---------------- device scratch ----------------
__device__ float g_H[(size_t)MAXA * H_DIM];
__device__ float g_Y[(size_t)MAXA * D_DIM];
__device__ int   g_bucket[E_NUM * MAXA];
__device__ int   g_cnt[E_NUM];
__device__ float g_wts[MAXA];

__device__ __forceinline__ uint32_t f2tf32(float f) {
    uint32_t u; asm("cvt.rna.tf32.f32 %0, %1;" : "=r"(u) : "f"(f)); return u;
}
__device__ __forceinline__ float gelu_exact(float v) {
    return 0.5f * v * (1.0f + erff(v * 0.70710678118654752f));
}
__device__ __forceinline__ void mma_tf32(float* d, const uint32_t* a, const uint32_t* b) {
    asm volatile(
        "mma.sync.aligned.m16n8k8.row.col.f32.tf32.tf32.f32 "
        "{%0,%1,%2,%3}, {%4,%5,%6,%7}, {%8,%9}, {%0,%1,%2,%3};"
        : "+f"(d[0]), "+f"(d[1]), "+f"(d[2]), "+f"(d[3])
        : "r"(a[0]), "r"(a[1]), "r"(a[2]), "r"(a[3]), "r"(b[0]), "r"(b[1]));
}

// ---------------- routing kernels ----------------
__global__ void zero_kernel() {
    if (threadIdx.x < E_NUM) g_cnt[threadIdx.x] = 0;
}

__global__ void gate_kernel(const float* __restrict__ x,
                            const float* __restrict__ Wg, int N) {
    int warp = (blockIdx.x * blockDim.x + threadIdx.x) >> 5;
    int lane = threadIdx.x & 31;
    if (warp >= N) return;
    const float* xr = x + (size_t)warp * D_DIM;
    float acc[E_NUM];
    #pragma unroll
    for (int e = 0; e < E_NUM; e++) acc[e] = 0.0f;
    for (int d = lane; d < D_DIM; d += 32) {
        float xv = xr[d];
        #pragma unroll
        for (int e = 0; e < E_NUM; e++) acc[e] += xv * Wg[e * D_DIM + d];
    }
    #pragma unroll
    for (int e = 0; e < E_NUM; e++)
        #pragma unroll
        for (int o = 16; o > 0; o >>= 1)
            acc[e] += __shfl_xor_sync(0xffffffffu, acc[e], o);
    if (lane == 0) {
        float m1 = -INFINITY, m2 = -INFINITY;
        int i1 = 0, i2 = 0;
        #pragma unroll
        for (int e = 0; e < E_NUM; e++) {
            float l = acc[e];
            if (l > m1)      { m2 = m1; i2 = i1; m1 = l; i1 = e; }
            else if (l > m2) { m2 = l; i2 = e; }
        }
        float e1 = expf(m2 - m1);
        float inv = 1.0f / (1.0f + e1);
        int a0 = warp * 2, a1 = warp * 2 + 1;
        g_wts[a0] = inv;
        g_wts[a1] = e1 * inv;
        int p0 = atomicAdd(&g_cnt[i1], 1);
        g_bucket[i1 * MAXA + p0] = a0;
        int p1 = atomicAdd(&g_cnt[i2], 1);
        g_bucket[i2 * MAXA + p1] = a1;
    }
}

// ---------------- tf32 mma.sync gathered GEMM ----------------
// GELU_EPI=true : A rows = x[token=a>>1], W=W1(E,H,D), bias=b1, out=g_H (rows=a)
// GELU_EPI=false: A rows = g_H[a],        W=W2(E,D,H), bias=b2, out=g_Y (rows=a), *g_wts[a]
template <int KDIM, int NOUT, bool GELU_EPI>
__global__ __launch_bounds__(256, 2)
void moe_mma_kernel(const float* __restrict__ x,
                    const float* __restrict__ W,
                    const float* __restrict__ bias) {
    constexpr int NCH = KDIM / BK;

    __shared__ float As[2][BK][LDA];   // K-major transposed: As[k][m]
    __shared__ float Bs[2][BK][LDA];   // Bs[k][n]
    __shared__ int   sh_aidx[BM];
    __shared__ int   sh_asrc[BM];
    __shared__ float sh_bias[BN];
    __shared__ float sh_wt[BM];

    int e = blockIdx.z;
    int cnt = g_cnt[e];
    int m0 = blockIdx.y * BM;
    if (m0 >= cnt) return;
    int n0 = blockIdx.x * BN;

    int tid = threadIdx.x;
    if (tid < BM) {
        int mi = m0 + tid;
        int a = (mi < cnt) ? g_bucket[e * MAXA + mi] : -1;
        sh_aidx[tid] = a;
        sh_asrc[tid] = (a >= 0) ? (GELU_EPI ? (a >> 1) : a) : 0;
        sh_wt[tid]   = (!GELU_EPI && a >= 0) ? g_wts[a] : 0.0f;
    } else {
        int c = tid - BM;
        sh_bias[c] = bias[(size_t)e * NOUT + n0 + c];
    }
    __syncthreads();

    const float* Asrc = GELU_EPI ? x : (const float*)g_H;
    const float* Wb   = W + (size_t)e * NOUT * KDIM;

    int l = tid & 31;
    int w = tid >> 5;
    int mbase = (w >> 2) * 64;   // warp tile 64x32
    int nbase = (w & 3) * 32;

    // loader mapping: idx = tid + it*256 over 512 float4 slots; row = idx&127, kslot j = idx>>7
    int lr[2], lj[2];
    const float* aptr[2];
    const float* bptr[2];
    #pragma unroll
    for (int it = 0; it < 2; it++) {
        int idx = tid + it * 256;
        lr[it] = idx & 127;
        lj[it] = idx >> 7;           // 0..3
        aptr[it] = Asrc + (size_t)sh_asrc[lr[it]] * KDIM + lj[it] * 4;
        bptr[it] = Wb + (size_t)(n0 + lr[it]) * KDIM + lj[it] * 4;
    }

    float acc[4][4][4];
    #pragma unroll
    for (int i = 0; i < 4; i++)
        #pragma unroll
        for (int j = 0; j < 4; j++)
            #pragma unroll
            for (int k = 0; k < 4; k++) acc[i][j][k] = 0.0f;

    // preload chunk 0
    #pragma unroll
    for (int it = 0; it < 2; it++) {
        float4 av = *(const float4*)(aptr[it]);
        float4 bv = *(const float4*)(bptr[it]);
        int kb = lj[it] * 4, r = lr[it];
        As[0][kb + 0][r] = __uint_as_float(f2tf32(av.x));
        As[0][kb + 1][r] = __uint_as_float(f2tf32(av.y));
        As[0][kb + 2][r] = __uint_as_float(f2tf32(av.z));
        As[0][kb + 3][r] = __uint_as_float(f2tf32(av.w));
        Bs[0][kb + 0][r] = __uint_as_float(f2tf32(bv.x));
        Bs[0][kb + 1][r] = __uint_as_float(f2tf32(bv.y));
        Bs[0][kb + 2][r] = __uint_as_float(f2tf32(bv.z));
        Bs[0][kb + 3][r] = __uint_as_float(f2tf32(bv.w));
    }
    __syncthreads();

    for (int c = 0; c < NCH; c++) {
        int s = c & 1;
        float4 av[2], bv[2];
        if (c + 1 < NCH) {
            #pragma unroll
            for (int it = 0; it < 2; it++) {
                av[it] = *(const float4*)(aptr[it] + (size_t)(c + 1) * BK);
                bv[it] = *(const float4*)(bptr[it] + (size_t)(c + 1) * BK);
            }
        }

        const uint32_t* Au = (const uint32_t*)&As[s][0][0];
        const uint32_t* Bu = (const uint32_t*)&Bs[s][0][0];
        #pragma unroll
        for (int ks = 0; ks < 2; ks++) {
            int kk = ks * 8;
            uint32_t af[4][4], bf[4][2];
            #pragma unroll
            for (int mf = 0; mf < 4; mf++) {
                int m = mbase + mf * 16 + (l >> 2);
                int kc = kk + (l & 3);
                af[mf][0] = Au[kc * LDA + m];
                af[mf][1] = Au[kc * LDA + m + 8];
                af[mf][2] = Au[(kc + 4) * LDA + m];
                af[mf][3] = Au[(kc + 4) * LDA + m + 8];
            }
            #pragma unroll
            for (int nf = 0; nf < 4; nf++) {
                int n = nbase + nf * 8 + (l >> 2);
                int kc = kk + (l & 3);
                bf[nf][0] = Bu[kc * LDA + n];
                bf[nf][1] = Bu[(kc + 4) * LDA + n];
            }
            #pragma unroll
            for (int mf = 0; mf < 4; mf++)
                #pragma unroll
                for (int nf = 0; nf < 4; nf++)
                    mma_tf32(acc[mf][nf], af[mf], bf[nf]);
        }

        if (c + 1 < NCH) {
            int so = s ^ 1;
            #pragma unroll
            for (int it = 0; it < 2; it++) {
                int kb = lj[it] * 4, r = lr[it];
                As[so][kb + 0][r] = __uint_as_float(f2tf32(av[it].x));
                As[so][kb + 1][r] = __uint_as_float(f2tf32(av[it].y));
                As[so][kb + 2][r] = __uint_as_float(f2tf32(av[it].z));
                As[so][kb + 3][r] = __uint_as_float(f2tf32(av[it].w));
                Bs[so][kb + 0][r] = __uint_as_float(f2tf32(bv[it].x));
                Bs[so][kb + 1][r] = __uint_as_float(f2tf32(bv[it].y));
                Bs[so][kb + 2][r] = __uint_as_float(f2tf32(bv[it].z));
                Bs[so][kb + 3][r] = __uint_as_float(f2tf32(bv[it].w));
            }
        }
        __syncthreads();
    }

    // epilogue: direct float2 stores to gathered rows
    float* outbase = GELU_EPI ? (float*)g_H : (float*)g_Y;
    #pragma unroll
    for (int mf = 0; mf < 4; mf++) {
        int r0 = mbase + mf * 16 + (l >> 2);
        int r1 = r0 + 8;
        int a0 = sh_aidx[r0];
        int a1 = sh_aidx[r1];
        float w0 = GELU_EPI ? 1.0f : sh_wt[r0];
        float w1 = GELU_EPI ? 1.0f : sh_wt[r1];
        #pragma unroll
        for (int nf = 0; nf < 4; nf++) {
            int cidx = nbase + nf * 8 + (l & 3) * 2;
            float b0c = sh_bias[cidx], b1c = sh_bias[cidx + 1];
            if (a0 >= 0) {
                float v0 = acc[mf][nf][0] + b0c;
                float v1 = acc[mf][nf][1] + b1c;
                if (GELU_EPI) { v0 = gelu_exact(v0); v1 = gelu_exact(v1); }
                else          { v0 *= w0; v1 *= w0; }
                *(float2*)(outbase + (size_t)a0 * NOUT + n0 + cidx) = make_float2(v0, v1);
            }
            if (a1 >= 0) {
                float v2 = acc[mf][nf][2] + b0c;
                float v3 = acc[mf][nf][3] + b1c;
                if (GELU_EPI) { v2 = gelu_exact(v2); v3 = gelu_exact(v3); }
                else          { v2 *= w1; v3 *= w1; }
                *(float2*)(outbase + (size_t)a1 * NOUT + n0 + cidx) = make_float2(v2, v3);
            }
        }
    }
}

// ---------------- combine ----------------
__global__ void combine_kernel(float* __restrict__ out, int N) {
    int i = blockIdx.x * blockDim.x + threadIdx.x;
    int total = N * (D_DIM / 4);
    if (i >= total) return;
    int n = i / (D_DIM / 4);
    int c = i - n * (D_DIM / 4);
    const float4* Y = (const float4*)g_Y;
    float4 a = Y[(size_t)(2 * n) * (D_DIM / 4) + c];
    float4 b = Y[(size_t)(2 * n + 1) * (D_DIM / 4) + c];
    ((float4*)out)[i] = make_float4(a.x + b.x, a.y + b.y, a.z + b.z, a.w + b.w);
}

// ---------------- launch ----------------
extern "C" void kernel_launch(void* const* d_in, const int* in_sizes, int n_in,
                              void* d_out, int out_size) {
    const float* x  = (const float*)d_in[0];
    const float* Wg = (const float*)d_in[1];
    const float* W1 = (const float*)d_in[2];
    const float* b1 = (const float*)d_in[3];
    const float* W2 = (const float*)d_in[4];
    const float* b2 = (const float*)d_in[5];
    float* out = (float*)d_out;
    int N = in_sizes[0] / D_DIM;   // 8192

    zero_kernel<<<1, 32>>>();
    gate_kernel<<<(N + 7) / 8, 256>>>(x, Wg, N);
    moe_mma_kernel<D_DIM, H_DIM, true >
        <<<dim3(H_DIM / BN, MAXA / BM, E_NUM), 256>>>(x, W1, b1);
    moe_mma_kernel<H_DIM, D_DIM, false>
        <<<dim3(D_DIM / BN, MAXA / BM, E_NUM), 256>>>(x, W2, b2);
    combine_kernel<<<(N * (D_DIM / 4) + 255) / 256, 256>>>(out, N);
}

// round 5
// speedup vs baseline: 2.6138x; 1.3957x over previous
#include <cuda_runtime.h>
#include <math.h>
#include <cstdint>

// Problem constants
#define D_DIM 1024
#define H_DIM 4096
#define E_NUM 8
#define MAXA  16384

// GEMM tiling
#define BM 128
#define BN 128
#define BK 16            // K elems per pipeline chunk (4 float4 slots)
#define NSTAGE 4
#define STAGE_BYTES 16384    // A 8KB + B 8KB
#define SMEM_DYN (NSTAGE * STAGE_BYTES + 2048)

// ---------------- device scratch ----------------
__device__ float g_H[(size_t)MAXA * H_DIM];
__device__ float g_Y[(size_t)MAXA * D_DIM];
__device__ int   g_bucket[E_NUM * MAXA];
__device__ int   g_cnt[E_NUM];
__device__ float g_wts[MAXA];

// ---------------- helpers ----------------
__device__ __forceinline__ uint32_t smem_u32(const void* p) {
    uint32_t a;
    asm("{ .reg .u64 t; cvta.to.shared.u64 t, %1; cvt.u32.u64 %0, t; }" : "=r"(a) : "l"(p));
    return a;
}
__device__ __forceinline__ uint32_t f2tf32(uint32_t fbits) {
    uint32_t u;
    asm("cvt.rna.tf32.f32 %0, %1;" : "=r"(u) : "r"(fbits));
    return u;
}
__device__ __forceinline__ float gelu_exact(float v) {
    return 0.5f * v * (1.0f + erff(v * 0.70710678118654752f));
}
__device__ __forceinline__ void mma_tf32(float* d, const uint32_t* a, const uint32_t* b) {
    asm volatile(
        "mma.sync.aligned.m16n8k8.row.col.f32.tf32.tf32.f32 "
        "{%0,%1,%2,%3}, {%4,%5,%6,%7}, {%8,%9}, {%0,%1,%2,%3};"
        : "+f"(d[0]), "+f"(d[1]), "+f"(d[2]), "+f"(d[3])
        : "r"(a[0]), "r"(a[1]), "r"(a[2]), "r"(a[3]), "r"(b[0]), "r"(b[1]));
}
__device__ __forceinline__ void ldsm_x4(uint32_t* r, uint32_t addr) {
    asm volatile("ldmatrix.sync.aligned.m8n8.x4.shared.b16 {%0,%1,%2,%3}, [%4];"
                 : "=r"(r[0]), "=r"(r[1]), "=r"(r[2]), "=r"(r[3]) : "r"(addr));
}
__device__ __forceinline__ void ldsm_x2(uint32_t* r, uint32_t addr) {
    asm volatile("ldmatrix.sync.aligned.m8n8.x2.shared.b16 {%0,%1}, [%2];"
                 : "=r"(r[0]), "=r"(r[1]) : "r"(addr));
}
__device__ __forceinline__ void cp_async16(uint32_t dst, const void* src) {
    asm volatile("cp.async.cg.shared.global [%0], [%1], 16;" :: "r"(dst), "l"(src));
}
#define CP_COMMIT() asm volatile("cp.async.commit_group;" ::: "memory")
#define CP_WAIT2()  asm volatile("cp.async.wait_group 2;" ::: "memory")

// swizzled offset within a tile: row r (0..127, 64B rows of 4 float4), slot s (0..3)
__device__ __forceinline__ uint32_t sw_off(int r, int s) {
    return (uint32_t)(r * 64 + ((s ^ ((r >> 1) & 3)) << 4));
}

// ---------------- routing kernels ----------------
__global__ void zero_kernel() {
    if (threadIdx.x < E_NUM) g_cnt[threadIdx.x] = 0;
}

__global__ void gate_kernel(const float* __restrict__ x,
                            const float* __restrict__ Wg, int N) {
    int warp = (blockIdx.x * blockDim.x + threadIdx.x) >> 5;
    int lane = threadIdx.x & 31;
    if (warp >= N) return;
    const float* xr = x + (size_t)warp * D_DIM;
    float acc[E_NUM];
    #pragma unroll
    for (int e = 0; e < E_NUM; e++) acc[e] = 0.0f;
    for (int d = lane; d < D_DIM; d += 32) {
        float xv = xr[d];
        #pragma unroll
        for (int e = 0; e < E_NUM; e++) acc[e] += xv * Wg[e * D_DIM + d];
    }
    #pragma unroll
    for (int e = 0; e < E_NUM; e++)
        #pragma unroll
        for (int o = 16; o > 0; o >>= 1)
            acc[e] += __shfl_xor_sync(0xffffffffu, acc[e], o);
    if (lane == 0) {
        float m1 = -INFINITY, m2 = -INFINITY;
        int i1 = 0, i2 = 0;
        #pragma unroll
        for (int e = 0; e < E_NUM; e++) {
            float l = acc[e];
            if (l > m1)      { m2 = m1; i2 = i1; m1 = l; i1 = e; }
            else if (l > m2) { m2 = l; i2 = e; }
        }
        float e1 = expf(m2 - m1);
        float inv = 1.0f / (1.0f + e1);
        int a0 = warp * 2, a1 = warp * 2 + 1;
        g_wts[a0] = inv;
        g_wts[a1] = e1 * inv;
        int p0 = atomicAdd(&g_cnt[i1], 1);
        g_bucket[i1 * MAXA + p0] = a0;
        int p1 = atomicAdd(&g_cnt[i2], 1);
        g_bucket[i2 * MAXA + p1] = a1;
    }
}

// ---------------- tf32 mma.sync gathered GEMM, cp.async 4-stage + ldmatrix ----------------
template <int KDIM, int NOUT, bool GELU_EPI>
__global__ __launch_bounds__(256, 2)
void moe_mma_kernel(const float* __restrict__ x,
                    const float* __restrict__ W,
                    const float* __restrict__ bias) {
    constexpr int NCH = KDIM / BK;

    extern __shared__ __align__(16) char dsm[];
    uint32_t sb = smem_u32(dsm);
    int*   sh_aidx = (int*)(dsm + NSTAGE * STAGE_BYTES);
    int*   sh_asrc = (int*)(dsm + NSTAGE * STAGE_BYTES + 512);
    float* sh_wt   = (float*)(dsm + NSTAGE * STAGE_BYTES + 1024);
    float* sh_bias = (float*)(dsm + NSTAGE * STAGE_BYTES + 1536);

    int e = blockIdx.z;
    int cnt = g_cnt[e];
    int m0 = blockIdx.y * BM;
    if (m0 >= cnt) return;
    int n0 = blockIdx.x * BN;
    int tid = threadIdx.x;

    if (tid < BM) {
        int mi = m0 + tid;
        int a = (mi < cnt) ? g_bucket[e * MAXA + mi] : -1;
        sh_aidx[tid] = a;
        sh_asrc[tid] = (a >= 0) ? (GELU_EPI ? (a >> 1) : a) : 0;
        sh_wt[tid]   = (!GELU_EPI && a >= 0) ? g_wts[a] : 0.0f;
    } else {
        int c = tid - BM;
        sh_bias[c] = bias[(size_t)e * NOUT + n0 + c];
    }
    __syncthreads();

    const float* Asrc = GELU_EPI ? x : (const float*)g_H;
    const float* Wb   = W + (size_t)e * NOUT * KDIM;

    // ---- loader mapping: thread -> 2 A rows + 2 B rows, fixed float4 slot ----
    int lks = tid & 3;            // float4 slot 0..3
    int lm0 = tid >> 2;           // row 0..63
    int lm1 = lm0 + 64;
    const float* aptr0 = Asrc + (size_t)sh_asrc[lm0] * KDIM + lks * 4;
    const float* aptr1 = Asrc + (size_t)sh_asrc[lm1] * KDIM + lks * 4;
    const float* bptr0 = Wb + (size_t)(n0 + lm0) * KDIM + lks * 4;
    const float* bptr1 = Wb + (size_t)(n0 + lm1) * KDIM + lks * 4;
    uint32_t dA0 = sw_off(lm0, lks);
    uint32_t dA1 = sw_off(lm1, lks);

    // prologue: fill stages 0..NSTAGE-2
    #pragma unroll
    for (int c = 0; c < NSTAGE - 1; c++) {
        uint32_t ab = sb + (uint32_t)c * STAGE_BYTES;
        uint32_t bb = ab + 8192u;
        size_t ko = (size_t)c * BK;
        cp_async16(ab + dA0, aptr0 + ko);
        cp_async16(ab + dA1, aptr1 + ko);
        cp_async16(bb + dA0, bptr0 + ko);
        cp_async16(bb + dA1, bptr1 + ko);
        CP_COMMIT();
    }

    // ---- fragment addressing ----
    int l = tid & 31;
    int w = tid >> 5;
    int mbase = (w >> 2) * 64;    // 2 warps along m
    int nbase = (w & 3) * 32;     // 4 warps along n
    int ahi = l >> 4;             // 0/1 -> which half-slot within k8 group
    int bhi = (l >> 3) & 1;
    uint32_t am64[4], axor[4];
    #pragma unroll
    for (int mf = 0; mf < 4; mf++) {
        int m = mbase + mf * 16 + (l & 15);
        am64[mf] = (uint32_t)(m * 64);
        axor[mf] = (uint32_t)((m >> 1) & 3);
    }
    uint32_t bn64[4], bxor[4];
    #pragma unroll
    for (int nf = 0; nf < 4; nf++) {
        int n = nbase + nf * 8 + (l & 7);
        bn64[nf] = (uint32_t)(n * 64);
        bxor[nf] = (uint32_t)((n >> 1) & 3);
    }

    float acc[4][4][4];
    #pragma unroll
    for (int i = 0; i < 4; i++)
        #pragma unroll
        for (int j = 0; j < 4; j++)
            #pragma unroll
            for (int k = 0; k < 4; k++) acc[i][j][k] = 0.0f;

    for (int c = 0; c < NCH; c++) {
        CP_WAIT2();
        __syncthreads();

        // issue chunk c+3 into stage (c+3)%4 (stage of c-1, already consumed)
        if (c + NSTAGE - 1 < NCH) {
            int cn = c + NSTAGE - 1;
            uint32_t ab = sb + (uint32_t)(cn & 3) * STAGE_BYTES;
            uint32_t bb = ab + 8192u;
            size_t ko = (size_t)cn * BK;
            cp_async16(ab + dA0, aptr0 + ko);
            cp_async16(ab + dA1, aptr1 + ko);
            cp_async16(bb + dA0, bptr0 + ko);
            cp_async16(bb + dA1, bptr1 + ko);
        }
        CP_COMMIT();

        uint32_t ab = sb + (uint32_t)(c & 3) * STAGE_BYTES;
        uint32_t bb = ab + 8192u;
        #pragma unroll
        for (int s = 0; s < 2; s++) {
            uint32_t af[4][4], bf[4][2];
            #pragma unroll
            for (int mf = 0; mf < 4; mf++) {
                uint32_t slot = (uint32_t)((s << 1) | ahi) ^ axor[mf];
                ldsm_x4(af[mf], ab + am64[mf] + (slot << 4));
            }
            #pragma unroll
            for (int nf = 0; nf < 4; nf++) {
                uint32_t slot = (uint32_t)((s << 1) | bhi) ^ bxor[nf];
                ldsm_x2(bf[nf], bb + bn64[nf] + (slot << 4));
            }
            #pragma unroll
            for (int mf = 0; mf < 4; mf++)
                #pragma unroll
                for (int i = 0; i < 4; i++) af[mf][i] = f2tf32(af[mf][i]);
            #pragma unroll
            for (int nf = 0; nf < 4; nf++) {
                bf[nf][0] = f2tf32(bf[nf][0]);
                bf[nf][1] = f2tf32(bf[nf][1]);
            }
            #pragma unroll
            for (int mf = 0; mf < 4; mf++)
                #pragma unroll
                for (int nf = 0; nf < 4; nf++)
                    mma_tf32(acc[mf][nf], af[mf], bf[nf]);
        }
        __syncthreads();
    }

    // ---- epilogue: direct float2 stores to gathered rows ----
    float* outbase = GELU_EPI ? (float*)g_H : (float*)g_Y;
    #pragma unroll
    for (int mf = 0; mf < 4; mf++) {
        int r0 = mbase + mf * 16 + (l >> 2);
        int r1 = r0 + 8;
        int a0 = sh_aidx[r0];
        int a1 = sh_aidx[r1];
        float w0 = GELU_EPI ? 1.0f : sh_wt[r0];
        float w1 = GELU_EPI ? 1.0f : sh_wt[r1];
        #pragma unroll
        for (int nf = 0; nf < 4; nf++) {
            int cidx = nbase + nf * 8 + (l & 3) * 2;
            float b0c = sh_bias[cidx], b1c = sh_bias[cidx + 1];
            if (a0 >= 0) {
                float v0 = acc[mf][nf][0] + b0c;
                float v1 = acc[mf][nf][1] + b1c;
                if (GELU_EPI) { v0 = gelu_exact(v0); v1 = gelu_exact(v1); }
                else          { v0 *= w0; v1 *= w0; }
                *(float2*)(outbase + (size_t)a0 * NOUT + n0 + cidx) = make_float2(v0, v1);
            }
            if (a1 >= 0) {
                float v2 = acc[mf][nf][2] + b0c;
                float v3 = acc[mf][nf][3] + b1c;
                if (GELU_EPI) { v2 = gelu_exact(v2); v3 = gelu_exact(v3); }
                else          { v2 *= w1; v3 *= w1; }
                *(float2*)(outbase + (size_t)a1 * NOUT + n0 + cidx) = make_float2(v2, v3);
            }
        }
    }
}

// ---------------- combine ----------------
__global__ void combine_kernel(float* __restrict__ out, int N) {
    int i = blockIdx.x * blockDim.x + threadIdx.x;
    int total = N * (D_DIM / 4);
    if (i >= total) return;
    int n = i / (D_DIM / 4);
    int c = i - n * (D_DIM / 4);
    const float4* Y = (const float4*)g_Y;
    float4 a = Y[(size_t)(2 * n) * (D_DIM / 4) + c];
    float4 b = Y[(size_t)(2 * n + 1) * (D_DIM / 4) + c];
    ((float4*)out)[i] = make_float4(a.x + b.x, a.y + b.y, a.z + b.z, a.w + b.w);
}

// ---------------- launch ----------------
extern "C" void kernel_launch(void* const* d_in, const int* in_sizes, int n_in,
                              void* d_out, int out_size) {
    const float* x  = (const float*)d_in[0];
    const float* Wg = (const float*)d_in[1];
    const float* W1 = (const float*)d_in[2];
    const float* b1 = (const float*)d_in[3];
    const float* W2 = (const float*)d_in[4];
    const float* b2 = (const float*)d_in[5];
    float* out = (float*)d_out;
    int N = in_sizes[0] / D_DIM;   // 8192

    cudaFuncSetAttribute(moe_mma_kernel<D_DIM, H_DIM, true>,
                         cudaFuncAttributeMaxDynamicSharedMemorySize, SMEM_DYN);
    cudaFuncSetAttribute(moe_mma_kernel<H_DIM, D_DIM, false>,
                         cudaFuncAttributeMaxDynamicSharedMemorySize, SMEM_DYN);

    zero_kernel<<<1, 32>>>();
    gate_kernel<<<(N + 7) / 8, 256>>>(x, Wg, N);
    moe_mma_kernel<D_DIM, H_DIM, true >
        <<<dim3(H_DIM / BN, MAXA / BM, E_NUM), 256, SMEM_DYN>>>(x, W1, b1);
    moe_mma_kernel<H_DIM, D_DIM, false>
        <<<dim3(D_DIM / BN, MAXA / BM, E_NUM), 256, SMEM_DYN>>>(x, W2, b2);
    combine_kernel<<<(N * (D_DIM / 4) + 255) / 256, 256>>>(out, N);
}

// round 7
// speedup vs baseline: 4.1099x; 1.5724x over previous
#include <cuda_runtime.h>
#include <math.h>
#include <cstdint>

// Problem constants
#define D_DIM 1024
#define H_DIM 4096
#define E_NUM 8
#define MAXA  16384
#define NTOK  8192

// GEMM tiling
#define BM 128
#define BN 128
#define BK 16            // K elems per pipeline chunk (4 float4 slots)
#define NSTAGE 4
#define STAGE_BYTES 16384    // A 8KB + B 8KB
#define SMEM_DYN (NSTAGE * STAGE_BYTES + 2048)

// ---------------- device scratch ----------------
__device__ float g_H[(size_t)MAXA * H_DIM];     // tf32-rounded gelu activations
__device__ float g_Y[(size_t)MAXA * D_DIM];
__device__ float g_W1c[(size_t)E_NUM * H_DIM * D_DIM];  // tf32-rounded W1
__device__ float g_W2c[(size_t)E_NUM * D_DIM * H_DIM];  // tf32-rounded W2
__device__ float g_Xc[(size_t)NTOK * D_DIM];            // tf32-rounded x
__device__ int   g_bucket[E_NUM * MAXA];
__device__ int   g_cnt[E_NUM];
__device__ float g_wts[MAXA];

// ---------------- helpers ----------------
__device__ __forceinline__ uint32_t smem_u32(const void* p) {
    uint32_t a;
    asm("{ .reg .u64 t; cvta.to.shared.u64 t, %1; cvt.u32.u64 %0, t; }" : "=r"(a) : "l"(p));
    return a;
}
__device__ __forceinline__ uint32_t f2tf32(uint32_t fbits) {
    uint32_t u;
    asm("cvt.rna.tf32.f32 %0, %1;" : "=r"(u) : "r"(fbits));
    return u;
}
__device__ __forceinline__ float f2tf32f(float f) {
    return __uint_as_float(f2tf32(__float_as_uint(f)));
}
__device__ __forceinline__ float gelu_exact(float v) {
    return 0.5f * v * (1.0f + erff(v * 0.70710678118654752f));
}
__device__ __forceinline__ void mma_tf32(float* d, const uint32_t* a, const uint32_t* b) {
    asm volatile(
        "mma.sync.aligned.m16n8k8.row.col.f32.tf32.tf32.f32 "
        "{%0,%1,%2,%3}, {%4,%5,%6,%7}, {%8,%9}, {%0,%1,%2,%3};"
        : "+f"(d[0]), "+f"(d[1]), "+f"(d[2]), "+f"(d[3])
        : "r"(a[0]), "r"(a[1]), "r"(a[2]), "r"(a[3]), "r"(b[0]), "r"(b[1]));
}
__device__ __forceinline__ void ldsm_x4(uint32_t* r, uint32_t addr) {
    asm volatile("ldmatrix.sync.aligned.m8n8.x4.shared.b16 {%0,%1,%2,%3}, [%4];"
                 : "=r"(r[0]), "=r"(r[1]), "=r"(r[2]), "=r"(r[3]) : "r"(addr));
}
__device__ __forceinline__ void ldsm_x2(uint32_t* r, uint32_t addr) {
    asm volatile("ldmatrix.sync.aligned.m8n8.x2.shared.b16 {%0,%1}, [%2];"
                 : "=r"(r[0]), "=r"(r[1]) : "r"(addr));
}
__device__ __forceinline__ void cp_async16(uint32_t dst, const void* src) {
    asm volatile("cp.async.cg.shared.global [%0], [%1], 16;" :: "r"(dst), "l"(src));
}
#define CP_COMMIT() asm volatile("cp.async.commit_group;" ::: "memory")
#define CP_WAIT2()  asm volatile("cp.async.wait_group 2;" ::: "memory")

// swizzled offset within a tile: row r (0..127, 64B rows of 4 float4), slot s (0..3)
__device__ __forceinline__ uint32_t sw_off(int r, int s) {
    return (uint32_t)(r * 64 + ((s ^ ((r >> 1) & 3)) << 4));
}

// ---------------- pre-convert fp32 -> tf32(rna) ----------------
__global__ void cvt_tf32_kernel(const float4* __restrict__ src,
                                float4* __restrict__ dst, int n4) {
    int i = blockIdx.x * blockDim.x + threadIdx.x;
    if (i >= n4) return;
    float4 v = src[i];
    v.x = f2tf32f(v.x); v.y = f2tf32f(v.y);
    v.z = f2tf32f(v.z); v.w = f2tf32f(v.w);
    dst[i] = v;
}

// ---------------- routing kernels ----------------
__global__ void zero_kernel() {
    if (threadIdx.x < E_NUM) g_cnt[threadIdx.x] = 0;
}

__global__ void gate_kernel(const float* __restrict__ x,
                            const float* __restrict__ Wg, int N) {
    int warp = (blockIdx.x * blockDim.x + threadIdx.x) >> 5;
    int lane = threadIdx.x & 31;
    if (warp >= N) return;
    const float* xr = x + (size_t)warp * D_DIM;
    float acc[E_NUM];
    #pragma unroll
    for (int e = 0; e < E_NUM; e++) acc[e] = 0.0f;
    for (int d = lane; d < D_DIM; d += 32) {
        float xv = xr[d];
        #pragma unroll
        for (int e = 0; e < E_NUM; e++) acc[e] += xv * Wg[e * D_DIM + d];
    }
    #pragma unroll
    for (int e = 0; e < E_NUM; e++)
        #pragma unroll
        for (int o = 16; o > 0; o >>= 1)
            acc[e] += __shfl_xor_sync(0xffffffffu, acc[e], o);
    if (lane == 0) {
        float m1 = -INFINITY, m2 = -INFINITY;
        int i1 = 0, i2 = 0;
        #pragma unroll
        for (int e = 0; e < E_NUM; e++) {
            float l = acc[e];
            if (l > m1)      { m2 = m1; i2 = i1; m1 = l; i1 = e; }
            else if (l > m2) { m2 = l; i2 = e; }
        }
        float e1 = expf(m2 - m1);
        float inv = 1.0f / (1.0f + e1);
        int a0 = warp * 2, a1 = warp * 2 + 1;
        g_wts[a0] = inv;
        g_wts[a1] = e1 * inv;
        int p0 = atomicAdd(&g_cnt[i1], 1);
        g_bucket[i1 * MAXA + p0] = a0;
        int p1 = atomicAdd(&g_cnt[i2], 1);
        g_bucket[i2 * MAXA + p1] = a1;
    }
}

// ---------------- tf32 mma.sync gathered GEMM, cp.async 4-stage + ldmatrix ----------------
// Inputs are already tf32-rounded; no cvt in the mainloop.
template <int KDIM, int NOUT, bool GELU_EPI>
__global__ __launch_bounds__(256, 2)
void moe_mma_kernel(const float* __restrict__ Asrc_in,
                    const float* __restrict__ W,
                    const float* __restrict__ bias) {
    constexpr int NCH = KDIM / BK;

    extern __shared__ __align__(16) char dsm[];
    uint32_t sb = smem_u32(dsm);
    int*   sh_aidx = (int*)(dsm + NSTAGE * STAGE_BYTES);
    int*   sh_asrc = (int*)(dsm + NSTAGE * STAGE_BYTES + 512);
    float* sh_wt   = (float*)(dsm + NSTAGE * STAGE_BYTES + 1024);
    float* sh_bias = (float*)(dsm + NSTAGE * STAGE_BYTES + 1536);

    int e = blockIdx.z;
    int cnt = g_cnt[e];
    int m0 = blockIdx.y * BM;
    if (m0 >= cnt) return;
    int n0 = blockIdx.x * BN;
    int tid = threadIdx.x;

    if (tid < BM) {
        int mi = m0 + tid;
        int a = (mi < cnt) ? g_bucket[e * MAXA + mi] : -1;
        sh_aidx[tid] = a;
        sh_asrc[tid] = (a >= 0) ? (GELU_EPI ? (a >> 1) : a) : 0;
        sh_wt[tid]   = (!GELU_EPI && a >= 0) ? g_wts[a] : 0.0f;
    } else {
        int c = tid - BM;
        sh_bias[c] = bias[(size_t)e * NOUT + n0 + c];
    }
    __syncthreads();

    const float* Asrc = Asrc_in;
    const float* Wb   = W + (size_t)e * NOUT * KDIM;

    // ---- loader mapping: thread -> 2 A rows + 2 B rows, fixed float4 slot ----
    int lks = tid & 3;            // float4 slot 0..3
    int lm0 = tid >> 2;           // row 0..63
    int lm1 = lm0 + 64;
    const float* aptr0 = Asrc + (size_t)sh_asrc[lm0] * KDIM + lks * 4;
    const float* aptr1 = Asrc + (size_t)sh_asrc[lm1] * KDIM + lks * 4;
    const float* bptr0 = Wb + (size_t)(n0 + lm0) * KDIM + lks * 4;
    const float* bptr1 = Wb + (size_t)(n0 + lm1) * KDIM + lks * 4;
    uint32_t dA0 = sw_off(lm0, lks);
    uint32_t dA1 = sw_off(lm1, lks);

    // prologue: fill stages 0..NSTAGE-2
    #pragma unroll
    for (int c = 0; c < NSTAGE - 1; c++) {
        uint32_t ab = sb + (uint32_t)c * STAGE_BYTES;
        uint32_t bb = ab + 8192u;
        size_t ko = (size_t)c * BK;
        cp_async16(ab + dA0, aptr0 + ko);
        cp_async16(ab + dA1, aptr1 + ko);
        cp_async16(bb + dA0, bptr0 + ko);
        cp_async16(bb + dA1, bptr1 + ko);
        CP_COMMIT();
    }

    // ---- fragment addressing ----
    int l = tid & 31;
    int w = tid >> 5;
    int mbase = (w >> 2) * 64;    // 2 warps along m
    int nbase = (w & 3) * 32;     // 4 warps along n
    int ahi = l >> 4;
    int bhi = (l >> 3) & 1;
    uint32_t am64[4], axor[4];
    #pragma unroll
    for (int mf = 0; mf < 4; mf++) {
        int m = mbase + mf * 16 + (l & 15);
        am64[mf] = (uint32_t)(m * 64);
        axor[mf] = (uint32_t)((m >> 1) & 3);
    }
    uint32_t bn64[4], bxor[4];
    #pragma unroll
    for (int nf = 0; nf < 4; nf++) {
        int n = nbase + nf * 8 + (l & 7);
        bn64[nf] = (uint32_t)(n * 64);
        bxor[nf] = (uint32_t)((n >> 1) & 3);
    }

    float acc[4][4][4];
    #pragma unroll
    for (int i = 0; i < 4; i++)
        #pragma unroll
        for (int j = 0; j < 4; j++)
            #pragma unroll
            for (int k = 0; k < 4; k++) acc[i][j][k] = 0.0f;

    for (int c = 0; c < NCH; c++) {
        CP_WAIT2();
        __syncthreads();

        if (c + NSTAGE - 1 < NCH) {
            int cn = c + NSTAGE - 1;
            uint32_t ab = sb + (uint32_t)(cn & 3) * STAGE_BYTES;
            uint32_t bb = ab + 8192u;
            size_t ko = (size_t)cn * BK;
            cp_async16(ab + dA0, aptr0 + ko);
            cp_async16(ab + dA1, aptr1 + ko);
            cp_async16(bb + dA0, bptr0 + ko);
            cp_async16(bb + dA1, bptr1 + ko);
        }
        CP_COMMIT();

        uint32_t ab = sb + (uint32_t)(c & 3) * STAGE_BYTES;
        uint32_t bb = ab + 8192u;
        #pragma unroll
        for (int s = 0; s < 2; s++) {
            uint32_t af[4][4], bf[4][2];
            #pragma unroll
            for (int mf = 0; mf < 4; mf++) {
                uint32_t slot = (uint32_t)((s << 1) | ahi) ^ axor[mf];
                ldsm_x4(af[mf], ab + am64[mf] + (slot << 4));
            }
            #pragma unroll
            for (int nf = 0; nf < 4; nf++) {
                uint32_t slot = (uint32_t)((s << 1) | bhi) ^ bxor[nf];
                ldsm_x2(bf[nf], bb + bn64[nf] + (slot << 4));
            }
            #pragma unroll
            for (int mf = 0; mf < 4; mf++)
                #pragma unroll
                for (int nf = 0; nf < 4; nf++)
                    mma_tf32(acc[mf][nf], af[mf], bf[nf]);
        }
        __syncthreads();
    }

    // ---- epilogue ----
    float* outbase = GELU_EPI ? (float*)g_H : (float*)g_Y;
    #pragma unroll
    for (int mf = 0; mf < 4; mf++) {
        int r0 = mbase + mf * 16 + (l >> 2);
        int r1 = r0 + 8;
        int a0 = sh_aidx[r0];
        int a1 = sh_aidx[r1];
        float w0 = GELU_EPI ? 1.0f : sh_wt[r0];
        float w1 = GELU_EPI ? 1.0f : sh_wt[r1];
        #pragma unroll
        for (int nf = 0; nf < 4; nf++) {
            int cidx = nbase + nf * 8 + (l & 3) * 2;
            float b0c = sh_bias[cidx], b1c = sh_bias[cidx + 1];
            if (a0 >= 0) {
                float v0 = acc[mf][nf][0] + b0c;
                float v1 = acc[mf][nf][1] + b1c;
                if (GELU_EPI) { v0 = f2tf32f(gelu_exact(v0)); v1 = f2tf32f(gelu_exact(v1)); }
                else          { v0 *= w0; v1 *= w0; }
                *(float2*)(outbase + (size_t)a0 * NOUT + n0 + cidx) = make_float2(v0, v1);
            }
            if (a1 >= 0) {
                float v2 = acc[mf][nf][2] + b0c;
                float v3 = acc[mf][nf][3] + b1c;
                if (GELU_EPI) { v2 = f2tf32f(gelu_exact(v2)); v3 = f2tf32f(gelu_exact(v3)); }
                else          { v2 *= w1; v3 *= w1; }
                *(float2*)(outbase + (size_t)a1 * NOUT + n0 + cidx) = make_float2(v2, v3);
            }
        }
    }
}

// ---------------- combine ----------------
__global__ void combine_kernel(float* __restrict__ out, int N) {
    int i = blockIdx.x * blockDim.x + threadIdx.x;
    int total = N * (D_DIM / 4);
    if (i >= total) return;
    int n = i / (D_DIM / 4);
    int c = i - n * (D_DIM / 4);
    const float4* Y = (const float4*)g_Y;
    float4 a = Y[(size_t)(2 * n) * (D_DIM / 4) + c];
    float4 b = Y[(size_t)(2 * n + 1) * (D_DIM / 4) + c];
    ((float4*)out)[i] = make_float4(a.x + b.x, a.y + b.y, a.z + b.z, a.w + b.w);
}

// ---------------- launch ----------------
extern "C" void kernel_launch(void* const* d_in, const int* in_sizes, int n_in,
                              void* d_out, int out_size) {
    const float* x  = (const float*)d_in[0];
    const float* Wg = (const float*)d_in[1];
    const float* W1 = (const float*)d_in[2];
    const float* b1 = (const float*)d_in[3];
    const float* W2 = (const float*)d_in[4];
    const float* b2 = (const float*)d_in[5];
    float* out = (float*)d_out;
    int N = in_sizes[0] / D_DIM;   // 8192

    cudaFuncSetAttribute(moe_mma_kernel<D_DIM, H_DIM, true>,
                         cudaFuncAttributeMaxDynamicSharedMemorySize, SMEM_DYN);
    cudaFuncSetAttribute(moe_mma_kernel<H_DIM, D_DIM, false>,
                         cudaFuncAttributeMaxDynamicSharedMemorySize, SMEM_DYN);

    float* w1c; cudaGetSymbolAddress((void**)&w1c, g_W1c);
    float* w2c; cudaGetSymbolAddress((void**)&w2c, g_W2c);
    float* xc;  cudaGetSymbolAddress((void**)&xc,  g_Xc);
    float* hbuf; cudaGetSymbolAddress((void**)&hbuf, g_H);

    int wn4 = (E_NUM * H_DIM * D_DIM) / 4;
    int xn4 = (N * D_DIM) / 4;
    cvt_tf32_kernel<<<(wn4 + 255) / 256, 256>>>((const float4*)W1, (float4*)w1c, wn4);
    cvt_tf32_kernel<<<(wn4 + 255) / 256, 256>>>((const float4*)W2, (float4*)w2c, wn4);
    cvt_tf32_kernel<<<(xn4 + 255) / 256, 256>>>((const float4*)x,  (float4*)xc,  xn4);

    zero_kernel<<<1, 32>>>();
    gate_kernel<<<(N + 7) / 8, 256>>>(x, Wg, N);
    moe_mma_kernel<D_DIM, H_DIM, true >
        <<<dim3(H_DIM / BN, MAXA / BM, E_NUM), 256, SMEM_DYN>>>(xc, w1c, b1);
    moe_mma_kernel<H_DIM, D_DIM, false>
        <<<dim3(D_DIM / BN, MAXA / BM, E_NUM), 256, SMEM_DYN>>>(hbuf, w2c, b2);
    combine_kernel<<<(N * (D_DIM / 4) + 255) / 256, 256>>>(out, N);
}

// round 8
// speedup vs baseline: 4.6522x; 1.1320x over previous
#include <cuda_runtime.h>
#include <math.h>
#include <cstdint>

// Problem constants
#define D_DIM 1024
#define H_DIM 4096
#define E_NUM 8
#define MAXA  16384
#define NTOK  8192

// GEMM tiling
#define BM 128
#define BN 128
#define BK 32                 // K elems per pipeline chunk (8 float4 slots, 128B rows)
#define NSTAGE 3
#define STAGE_BYTES 32768     // A 16KB + B 16KB
#define SMEM_DYN (NSTAGE * STAGE_BYTES + 2048)

// ---------------- device scratch ----------------
__device__ float g_H[(size_t)MAXA * H_DIM];     // tf32-rounded gelu activations
__device__ float g_Y[(size_t)MAXA * D_DIM];
__device__ float g_W1c[(size_t)E_NUM * H_DIM * D_DIM];  // tf32-rounded W1
__device__ float g_W2c[(size_t)E_NUM * D_DIM * H_DIM];  // tf32-rounded W2
__device__ float g_Xc[(size_t)NTOK * D_DIM];            // tf32-rounded x
__device__ int   g_bucket[E_NUM * MAXA];
__device__ int   g_cnt[E_NUM];
__device__ float g_wts[MAXA];

// ---------------- helpers ----------------
__device__ __forceinline__ uint32_t smem_u32(const void* p) {
    uint32_t a;
    asm("{ .reg .u64 t; cvta.to.shared.u64 t, %1; cvt.u32.u64 %0, t; }" : "=r"(a) : "l"(p));
    return a;
}
__device__ __forceinline__ uint32_t f2tf32(uint32_t fbits) {
    uint32_t u;
    asm("cvt.rna.tf32.f32 %0, %1;" : "=r"(u) : "r"(fbits));
    return u;
}
__device__ __forceinline__ float f2tf32f(float f) {
    return __uint_as_float(f2tf32(__float_as_uint(f)));
}
__device__ __forceinline__ float gelu_exact(float v) {
    return 0.5f * v * (1.0f + erff(v * 0.70710678118654752f));
}
__device__ __forceinline__ void mma_tf32(float* d, const uint32_t* a, const uint32_t* b) {
    asm volatile(
        "mma.sync.aligned.m16n8k8.row.col.f32.tf32.tf32.f32 "
        "{%0,%1,%2,%3}, {%4,%5,%6,%7}, {%8,%9}, {%0,%1,%2,%3};"
        : "+f"(d[0]), "+f"(d[1]), "+f"(d[2]), "+f"(d[3])
        : "r"(a[0]), "r"(a[1]), "r"(a[2]), "r"(a[3]), "r"(b[0]), "r"(b[1]));
}
__device__ __forceinline__ void ldsm_x4(uint32_t* r, uint32_t addr) {
    asm volatile("ldmatrix.sync.aligned.m8n8.x4.shared.b16 {%0,%1,%2,%3}, [%4];"
                 : "=r"(r[0]), "=r"(r[1]), "=r"(r[2]), "=r"(r[3]) : "r"(addr));
}
__device__ __forceinline__ void cp_async16(uint32_t dst, const void* src) {
    asm volatile("cp.async.cg.shared.global [%0], [%1], 16;" :: "r"(dst), "l"(src));
}
#define CP_COMMIT() asm volatile("cp.async.commit_group;" ::: "memory")
#define CP_WAIT1()  asm volatile("cp.async.wait_group 1;" ::: "memory")

// swizzled byte offset within a tile: row r (0..127, 128B rows), slot s (0..7)
__device__ __forceinline__ uint32_t sw_off(int r, int s) {
    return (uint32_t)(r * 128 + ((s ^ (r & 7)) << 4));
}

// ---------------- pre-convert fp32 -> tf32(rna) ----------------
__global__ void cvt_tf32_kernel(const float4* __restrict__ src,
                                float4* __restrict__ dst, int n4) {
    int i = blockIdx.x * blockDim.x + threadIdx.x;
    if (i >= n4) return;
    float4 v = src[i];
    v.x = f2tf32f(v.x); v.y = f2tf32f(v.y);
    v.z = f2tf32f(v.z); v.w = f2tf32f(v.w);
    dst[i] = v;
}

// ---------------- routing kernels ----------------
__global__ void zero_kernel() {
    if (threadIdx.x < E_NUM) g_cnt[threadIdx.x] = 0;
}

__global__ void gate_kernel(const float* __restrict__ x,
                            const float* __restrict__ Wg, int N) {
    int warp = (blockIdx.x * blockDim.x + threadIdx.x) >> 5;
    int lane = threadIdx.x & 31;
    if (warp >= N) return;
    const float* xr = x + (size_t)warp * D_DIM;
    float acc[E_NUM];
    #pragma unroll
    for (int e = 0; e < E_NUM; e++) acc[e] = 0.0f;
    for (int d = lane; d < D_DIM; d += 32) {
        float xv = xr[d];
        #pragma unroll
        for (int e = 0; e < E_NUM; e++) acc[e] += xv * Wg[e * D_DIM + d];
    }
    #pragma unroll
    for (int e = 0; e < E_NUM; e++)
        #pragma unroll
        for (int o = 16; o > 0; o >>= 1)
            acc[e] += __shfl_xor_sync(0xffffffffu, acc[e], o);
    if (lane == 0) {
        float m1 = -INFINITY, m2 = -INFINITY;
        int i1 = 0, i2 = 0;
        #pragma unroll
        for (int e = 0; e < E_NUM; e++) {
            float l = acc[e];
            if (l > m1)      { m2 = m1; i2 = i1; m1 = l; i1 = e; }
            else if (l > m2) { m2 = l; i2 = e; }
        }
        float e1 = expf(m2 - m1);
        float inv = 1.0f / (1.0f + e1);
        int a0 = warp * 2, a1 = warp * 2 + 1;
        g_wts[a0] = inv;
        g_wts[a1] = e1 * inv;
        int p0 = atomicAdd(&g_cnt[i1], 1);
        g_bucket[i1 * MAXA + p0] = a0;
        int p1 = atomicAdd(&g_cnt[i2], 1);
        g_bucket[i2 * MAXA + p1] = a1;
    }
}

// ---------------- tf32 mma.sync gathered GEMM, BK=32, 3-stage cp.async ----------------
template <int KDIM, int NOUT, bool GELU_EPI>
__global__ __launch_bounds__(256, 2)
void moe_mma_kernel(const float* __restrict__ Asrc,
                    const float* __restrict__ W,
                    const float* __restrict__ bias) {
    constexpr int NCH = KDIM / BK;

    extern __shared__ __align__(16) char dsm[];
    uint32_t sb = smem_u32(dsm);
    int*   sh_aidx = (int*)(dsm + NSTAGE * STAGE_BYTES);
    int*   sh_asrc = (int*)(dsm + NSTAGE * STAGE_BYTES + 512);
    float* sh_wt   = (float*)(dsm + NSTAGE * STAGE_BYTES + 1024);
    float* sh_bias = (float*)(dsm + NSTAGE * STAGE_BYTES + 1536);

    int e = blockIdx.z;
    int cnt = g_cnt[e];
    int m0 = blockIdx.y * BM;
    if (m0 >= cnt) return;
    int n0 = blockIdx.x * BN;
    int tid = threadIdx.x;

    if (tid < BM) {
        int mi = m0 + tid;
        int a = (mi < cnt) ? g_bucket[e * MAXA + mi] : -1;
        sh_aidx[tid] = a;
        sh_asrc[tid] = (a >= 0) ? (GELU_EPI ? (a >> 1) : a) : 0;
        sh_wt[tid]   = (!GELU_EPI && a >= 0) ? g_wts[a] : 0.0f;
    } else {
        int c = tid - BM;
        sh_bias[c] = bias[(size_t)e * NOUT + n0 + c];
    }
    __syncthreads();

    const float* Wb = W + (size_t)e * NOUT * KDIM;

    // ---- loader mapping: slot = tid&7, rows = (tid>>3) + 32j ----
    int ls = tid & 7;
    int lr = tid >> 3;                 // 0..31
    uint32_t aoff[4], boff[4], dsw[4];
    #pragma unroll
    for (int j = 0; j < 4; j++) {
        int r = lr + 32 * j;
        aoff[j] = (uint32_t)(sh_asrc[r] * KDIM + ls * 4);
        boff[j] = (uint32_t)((n0 + r) * KDIM + ls * 4);
        dsw[j]  = sw_off(r, ls);
    }

    // prologue: fill stages 0..NSTAGE-2
    #pragma unroll
    for (int c = 0; c < NSTAGE - 1; c++) {
        uint32_t ab = sb + (uint32_t)c * STAGE_BYTES;
        uint32_t bb = ab + 16384u;
        uint32_t ko = (uint32_t)c * BK;
        #pragma unroll
        for (int j = 0; j < 4; j++) {
            cp_async16(ab + dsw[j], Asrc + (size_t)(aoff[j] + ko));
            cp_async16(bb + dsw[j], Wb + (size_t)(boff[j] + ko));
        }
        CP_COMMIT();
    }

    // ---- fragment addressing ----
    int l = tid & 31;
    int w = tid >> 5;
    int mbase = (w >> 2) * 64;    // 2 warps along m
    int nbase = (w & 3) * 32;     // 4 warps along n
    int akey = l & 7;
    int ahib = l >> 4;
    uint32_t am128[4];
    #pragma unroll
    for (int mf = 0; mf < 4; mf++)
        am128[mf] = (uint32_t)((mbase + mf * 16 + (l & 15)) * 128);
    uint32_t bn128[4];
    #pragma unroll
    for (int nf = 0; nf < 4; nf++)
        bn128[nf] = (uint32_t)((nbase + nf * 8 + (l & 7)) * 128);
    uint32_t bq = (uint32_t)((l >> 3) & 3);   // mat index within B x4

    float acc[4][4][4];
    #pragma unroll
    for (int i = 0; i < 4; i++)
        #pragma unroll
        for (int j = 0; j < 4; j++)
            #pragma unroll
            for (int k = 0; k < 4; k++) acc[i][j][k] = 0.0f;

    for (int c = 0; c < NCH; c++) {
        CP_WAIT1();
        __syncthreads();

        if (c + NSTAGE - 1 < NCH) {
            int cn = c + NSTAGE - 1;
            uint32_t ab = sb + (uint32_t)(cn % NSTAGE) * STAGE_BYTES;
            uint32_t bb = ab + 16384u;
            uint32_t ko = (uint32_t)cn * BK;
            #pragma unroll
            for (int j = 0; j < 4; j++) {
                cp_async16(ab + dsw[j], Asrc + (size_t)(aoff[j] + ko));
                cp_async16(bb + dsw[j], Wb + (size_t)(boff[j] + ko));
            }
        }
        CP_COMMIT();

        uint32_t ab = sb + (uint32_t)(c % NSTAGE) * STAGE_BYTES;
        uint32_t bb = ab + 16384u;
        #pragma unroll
        for (int p = 0; p < 2; p++) {
            // B fragments for k8-steps 2p and 2p+1 in one x4 each
            uint32_t bf[4][4];
            #pragma unroll
            for (int nf = 0; nf < 4; nf++) {
                uint32_t slot = (((uint32_t)p << 2) | bq) ^ (uint32_t)akey;
                ldsm_x4(bf[nf], bb + bn128[nf] + (slot << 4));
            }
            #pragma unroll
            for (int sh = 0; sh < 2; sh++) {
                int s = 2 * p + sh;
                uint32_t af[4][4];
                #pragma unroll
                for (int mf = 0; mf < 4; mf++) {
                    uint32_t slot = (uint32_t)(((s << 1) | ahib) ^ akey);
                    ldsm_x4(af[mf], ab + am128[mf] + (slot << 4));
                }
                #pragma unroll
                for (int mf = 0; mf < 4; mf++)
                    #pragma unroll
                    for (int nf = 0; nf < 4; nf++)
                        mma_tf32(acc[mf][nf], af[mf], &bf[nf][2 * sh]);
            }
        }
    }

    // ---- epilogue ----
    __syncthreads();   // last stage reads done before anything else (uniform exit)
    float* outbase = GELU_EPI ? (float*)g_H : (float*)g_Y;
    #pragma unroll
    for (int mf = 0; mf < 4; mf++) {
        int r0 = mbase + mf * 16 + (l >> 2);
        int r1 = r0 + 8;
        int a0 = sh_aidx[r0];
        int a1 = sh_aidx[r1];
        float w0 = GELU_EPI ? 1.0f : sh_wt[r0];
        float w1 = GELU_EPI ? 1.0f : sh_wt[r1];
        #pragma unroll
        for (int nf = 0; nf < 4; nf++) {
            int cidx = nbase + nf * 8 + (l & 3) * 2;
            float b0c = sh_bias[cidx], b1c = sh_bias[cidx + 1];
            if (a0 >= 0) {
                float v0 = acc[mf][nf][0] + b0c;
                float v1 = acc[mf][nf][1] + b1c;
                if (GELU_EPI) { v0 = f2tf32f(gelu_exact(v0)); v1 = f2tf32f(gelu_exact(v1)); }
                else          { v0 *= w0; v1 *= w0; }
                *(float2*)(outbase + (size_t)a0 * NOUT + n0 + cidx) = make_float2(v0, v1);
            }
            if (a1 >= 0) {
                float v2 = acc[mf][nf][2] + b0c;
                float v3 = acc[mf][nf][3] + b1c;
                if (GELU_EPI) { v2 = f2tf32f(gelu_exact(v2)); v3 = f2tf32f(gelu_exact(v3)); }
                else          { v2 *= w1; v3 *= w1; }
                *(float2*)(outbase + (size_t)a1 * NOUT + n0 + cidx) = make_float2(v2, v3);
            }
        }
    }
}

// ---------------- combine ----------------
__global__ void combine_kernel(float* __restrict__ out, int N) {
    int i = blockIdx.x * blockDim.x + threadIdx.x;
    int total = N * (D_DIM / 4);
    if (i >= total) return;
    int n = i / (D_DIM / 4);
    int c = i - n * (D_DIM / 4);
    const float4* Y = (const float4*)g_Y;
    float4 a = Y[(size_t)(2 * n) * (D_DIM / 4) + c];
    float4 b = Y[(size_t)(2 * n + 1) * (D_DIM / 4) + c];
    ((float4*)out)[i] = make_float4(a.x + b.x, a.y + b.y, a.z + b.z, a.w + b.w);
}

// ---------------- launch ----------------
extern "C" void kernel_launch(void* const* d_in, const int* in_sizes, int n_in,
                              void* d_out, int out_size) {
    const float* x  = (const float*)d_in[0];
    const float* Wg = (const float*)d_in[1];
    const float* W1 = (const float*)d_in[2];
    const float* b1 = (const float*)d_in[3];
    const float* W2 = (const float*)d_in[4];
    const float* b2 = (const float*)d_in[5];
    float* out = (float*)d_out;
    int N = in_sizes[0] / D_DIM;   // 8192

    cudaFuncSetAttribute(moe_mma_kernel<D_DIM, H_DIM, true>,
                         cudaFuncAttributeMaxDynamicSharedMemorySize, SMEM_DYN);
    cudaFuncSetAttribute(moe_mma_kernel<H_DIM, D_DIM, false>,
                         cudaFuncAttributeMaxDynamicSharedMemorySize, SMEM_DYN);

    float* w1c; cudaGetSymbolAddress((void**)&w1c, g_W1c);
    float* w2c; cudaGetSymbolAddress((void**)&w2c, g_W2c);
    float* xc;  cudaGetSymbolAddress((void**)&xc,  g_Xc);
    float* hbuf; cudaGetSymbolAddress((void**)&hbuf, g_H);

    int wn4 = (E_NUM * H_DIM * D_DIM) / 4;
    int xn4 = (N * D_DIM) / 4;
    cvt_tf32_kernel<<<(wn4 + 255) / 256, 256>>>((const float4*)W1, (float4*)w1c, wn4);
    cvt_tf32_kernel<<<(wn4 + 255) / 256, 256>>>((const float4*)W2, (float4*)w2c, wn4);
    cvt_tf32_kernel<<<(xn4 + 255) / 256, 256>>>((const float4*)x,  (float4*)xc,  xn4);

    zero_kernel<<<1, 32>>>();
    gate_kernel<<<(N + 7) / 8, 256>>>(x, Wg, N);
    moe_mma_kernel<D_DIM, H_DIM, true >
        <<<dim3(H_DIM / BN, MAXA / BM, E_NUM), 256, SMEM_DYN>>>(xc, w1c, b1);
    moe_mma_kernel<H_DIM, D_DIM, false>
        <<<dim3(D_DIM / BN, MAXA / BM, E_NUM), 256, SMEM_DYN>>>(hbuf, w2c, b2);
    combine_kernel<<<(N * (D_DIM / 4) + 255) / 256, 256>>>(out, N);
}

// round 11
// speedup vs baseline: 8.1863x; 1.7597x over previous
#include <cuda_runtime.h>
#include <cuda_fp16.h>
#include <math.h>
#include <cstdint>

// Problem constants
#define D_DIM 1024
#define H_DIM 4096
#define E_NUM 8
#define MAXA  16384
#define NTOK  8192

// GEMM tiling (fp16: BK=64 elems = 128B rows)
#define BM 128
#define BN 128
#define BK 64
#define NSTAGE 3
#define STAGE_BYTES 32768     // A 16KB + B 16KB
#define SMEM_DYN (NSTAGE * STAGE_BYTES + 2048)

// ---------------- device scratch ----------------
__device__ __half g_H[(size_t)MAXA * H_DIM];             // fp16 gelu activations
__device__ float  g_Y[(size_t)MAXA * D_DIM];
__device__ __half g_W1c[(size_t)E_NUM * H_DIM * D_DIM];  // fp16 W1
__device__ __half g_W2c[(size_t)E_NUM * D_DIM * H_DIM];  // fp16 W2
__device__ __half g_Xc[(size_t)NTOK * D_DIM];            // fp16 x
__device__ int    g_bucket[E_NUM * MAXA];
__device__ int    g_cnt[E_NUM];
__device__ float  g_wts[MAXA];

// ---------------- helpers ----------------
__device__ __forceinline__ uint32_t smem_u32(const void* p) {
    uint32_t a;
    asm("{ .reg .u64 t; cvta.to.shared.u64 t, %1; cvt.u32.u64 %0, t; }" : "=r"(a) : "l"(p));
    return a;
}
__device__ __forceinline__ float gelu_exact(float v) {
    return 0.5f * v * (1.0f + erff(v * 0.70710678118654752f));
}
__device__ __forceinline__ void mma_f16(float* d, const uint32_t* a, const uint32_t* b) {
    asm volatile(
        "mma.sync.aligned.m16n8k16.row.col.f32.f16.f16.f32 "
        "{%0,%1,%2,%3}, {%4,%5,%6,%7}, {%8,%9}, {%0,%1,%2,%3};"
        : "+f"(d[0]), "+f"(d[1]), "+f"(d[2]), "+f"(d[3])
        : "r"(a[0]), "r"(a[1]), "r"(a[2]), "r"(a[3]), "r"(b[0]), "r"(b[1]));
}
__device__ __forceinline__ void ldsm_x4(uint32_t* r, uint32_t addr) {
    asm volatile("ldmatrix.sync.aligned.m8n8.x4.shared.b16 {%0,%1,%2,%3}, [%4];"
                 : "=r"(r[0]), "=r"(r[1]), "=r"(r[2]), "=r"(r[3]) : "r"(addr));
}
__device__ __forceinline__ void cp_async16(uint32_t dst, const void* src) {
    asm volatile("cp.async.cg.shared.global [%0], [%1], 16;" :: "r"(dst), "l"(src));
}
#define CP_COMMIT() asm volatile("cp.async.commit_group;" ::: "memory")
#define CP_WAIT1()  asm volatile("cp.async.wait_group 1;" ::: "memory")

// swizzled byte offset within a tile: row r (0..127, 128B rows), slot s (0..7, 16B granules)
__device__ __forceinline__ uint32_t sw_off(int r, int s) {
    return (uint32_t)(r * 128 + ((s ^ (r & 7)) << 4));
}

// ---------------- pre-convert fp32 -> fp16(rn) ----------------
__global__ void cvt_f16_kernel(const float4* __restrict__ src,
                               __half2* __restrict__ dst, int n4) {
    int i = blockIdx.x * blockDim.x + threadIdx.x;
    if (i >= n4) return;
    float4 v = src[i];
    dst[2 * i + 0] = __floats2half2_rn(v.x, v.y);
    dst[2 * i + 1] = __floats2half2_rn(v.z, v.w);
}

// ---------------- routing kernels ----------------
__global__ void zero_kernel() {
    if (threadIdx.x < E_NUM) g_cnt[threadIdx.x] = 0;
}

__global__ void gate_kernel(const float* __restrict__ x,
                            const float* __restrict__ Wg, int N) {
    int warp = (blockIdx.x * blockDim.x + threadIdx.x) >> 5;
    int lane = threadIdx.x & 31;
    if (warp >= N) return;
    const float* xr = x + (size_t)warp * D_DIM;
    float acc[E_NUM];
    #pragma unroll
    for (int e = 0; e < E_NUM; e++) acc[e] = 0.0f;
    for (int d = lane; d < D_DIM; d += 32) {
        float xv = xr[d];
        #pragma unroll
        for (int e = 0; e < E_NUM; e++) acc[e] += xv * Wg[e * D_DIM + d];
    }
    #pragma unroll
    for (int e = 0; e < E_NUM; e++)
        #pragma unroll
        for (int o = 16; o > 0; o >>= 1)
            acc[e] += __shfl_xor_sync(0xffffffffu, acc[e], o);
    if (lane == 0) {
        float m1 = -INFINITY, m2 = -INFINITY;
        int i1 = 0, i2 = 0;
        #pragma unroll
        for (int e = 0; e < E_NUM; e++) {
            float l = acc[e];
            if (l > m1)      { m2 = m1; i2 = i1; m1 = l; i1 = e; }
            else if (l > m2) { m2 = l; i2 = e; }
        }
        float e1 = expf(m2 - m1);
        float inv = 1.0f / (1.0f + e1);
        int a0 = warp * 2, a1 = warp * 2 + 1;
        g_wts[a0] = inv;
        g_wts[a1] = e1 * inv;
        int p0 = atomicAdd(&g_cnt[i1], 1);
        g_bucket[i1 * MAXA + p0] = a0;
        int p1 = atomicAdd(&g_cnt[i2], 1);
        g_bucket[i2 * MAXA + p1] = a1;
    }
}

// ---------------- fp16 mma.sync gathered GEMM, BK=64, 3-stage cp.async ----------------
template <int KDIM, int NOUT, bool GELU_EPI>
__global__ __launch_bounds__(256, 2)
void moe_mma_kernel(const __half* __restrict__ Asrc,
                    const __half* __restrict__ W,
                    const float* __restrict__ bias) {
    constexpr int NCH = KDIM / BK;

    extern __shared__ __align__(16) char dsm[];
    uint32_t sb = smem_u32(dsm);
    int*   sh_aidx = (int*)(dsm + NSTAGE * STAGE_BYTES);
    int*   sh_asrc = (int*)(dsm + NSTAGE * STAGE_BYTES + 512);
    float* sh_wt   = (float*)(dsm + NSTAGE * STAGE_BYTES + 1024);
    float* sh_bias = (float*)(dsm + NSTAGE * STAGE_BYTES + 1536);

    int e = blockIdx.z;
    int cnt = g_cnt[e];
    int m0 = blockIdx.y * BM;
    if (m0 >= cnt) return;
    int n0 = blockIdx.x * BN;
    int tid = threadIdx.x;

    if (tid < BM) {
        int mi = m0 + tid;
        int a = (mi < cnt) ? g_bucket[e * MAXA + mi] : -1;
        sh_aidx[tid] = a;
        sh_asrc[tid] = (a >= 0) ? (GELU_EPI ? (a >> 1) : a) : 0;
        sh_wt[tid]   = (!GELU_EPI && a >= 0) ? g_wts[a] : 0.0f;
    } else {
        int c = tid - BM;
        sh_bias[c] = bias[(size_t)e * NOUT + n0 + c];
    }
    __syncthreads();

    const __half* Wb = W + (size_t)e * NOUT * KDIM;

    // ---- loader mapping: slot = tid&7 (8 fp16 each), rows = (tid>>3) + 32j ----
    int ls = tid & 7;
    int lr = tid >> 3;                 // 0..31
    uint32_t aoff[4], boff[4], dsw[4];
    #pragma unroll
    for (int j = 0; j < 4; j++) {
        int r = lr + 32 * j;
        aoff[j] = (uint32_t)(sh_asrc[r] * KDIM + ls * 8);
        boff[j] = (uint32_t)((n0 + r) * KDIM + ls * 8);
        dsw[j]  = sw_off(r, ls);
    }

    // prologue: fill stages 0..NSTAGE-2
    #pragma unroll
    for (int c = 0; c < NSTAGE - 1; c++) {
        uint32_t ab = sb + (uint32_t)c * STAGE_BYTES;
        uint32_t bb = ab + 16384u;
        uint32_t ko = (uint32_t)c * BK;
        #pragma unroll
        for (int j = 0; j < 4; j++) {
            cp_async16(ab + dsw[j], Asrc + (size_t)(aoff[j] + ko));
            cp_async16(bb + dsw[j], Wb + (size_t)(boff[j] + ko));
        }
        CP_COMMIT();
    }

    // ---- fragment addressing ----
    int l = tid & 31;
    int w = tid >> 5;
    int mbase = (w >> 2) * 64;    // 2 warps along m
    int nbase = (w & 3) * 32;     // 4 warps along n
    int akey = l & 7;
    int ahib = l >> 4;
    uint32_t am128[4];
    #pragma unroll
    for (int mf = 0; mf < 4; mf++)
        am128[mf] = (uint32_t)((mbase + mf * 16 + (l & 15)) * 128);
    uint32_t bn128[4];
    #pragma unroll
    for (int nf = 0; nf < 4; nf++)
        bn128[nf] = (uint32_t)((nbase + nf * 8 + (l & 7)) * 128);
    uint32_t bq = (uint32_t)((l >> 3) & 3);   // mat index within B x4

    float acc[4][4][4];
    #pragma unroll
    for (int i = 0; i < 4; i++)
        #pragma unroll
        for (int j = 0; j < 4; j++)
            #pragma unroll
            for (int k = 0; k < 4; k++) acc[i][j][k] = 0.0f;

    for (int c = 0; c < NCH; c++) {
        CP_WAIT1();
        __syncthreads();

        if (c + NSTAGE - 1 < NCH) {
            int cn = c + NSTAGE - 1;
            uint32_t ab = sb + (uint32_t)(cn % NSTAGE) * STAGE_BYTES;
            uint32_t bb = ab + 16384u;
            uint32_t ko = (uint32_t)cn * BK;
            #pragma unroll
            for (int j = 0; j < 4; j++) {
                cp_async16(ab + dsw[j], Asrc + (size_t)(aoff[j] + ko));
                cp_async16(bb + dsw[j], Wb + (size_t)(boff[j] + ko));
            }
        }
        CP_COMMIT();

        uint32_t ab = sb + (uint32_t)(c % NSTAGE) * STAGE_BYTES;
        uint32_t bb = ab + 16384u;
        // 4 k16-steps per chunk; p covers 2 k-steps (B via one x4 per nf)
        #pragma unroll
        for (int p = 0; p < 2; p++) {
            uint32_t bf[4][4];
            #pragma unroll
            for (int nf = 0; nf < 4; nf++) {
                uint32_t slot = (((uint32_t)p << 2) | bq) ^ (uint32_t)akey;
                ldsm_x4(bf[nf], bb + bn128[nf] + (slot << 4));
            }
            #pragma unroll
            for (int sh = 0; sh < 2; sh++) {
                int s = 2 * p + sh;         // k16-step index 0..3
                uint32_t af[4][4];
                #pragma unroll
                for (int mf = 0; mf < 4; mf++) {
                    uint32_t slot = (uint32_t)(((s << 1) | ahib) ^ akey);
                    ldsm_x4(af[mf], ab + am128[mf] + (slot << 4));
                }
                #pragma unroll
                for (int mf = 0; mf < 4; mf++)
                    #pragma unroll
                    for (int nf = 0; nf < 4; nf++)
                        mma_f16(acc[mf][nf], af[mf], &bf[nf][2 * sh]);
            }
        }
    }

    // ---- epilogue ----
    __syncthreads();
    #pragma unroll
    for (int mf = 0; mf < 4; mf++) {
        int r0 = mbase + mf * 16 + (l >> 2);
        int r1 = r0 + 8;
        int a0 = sh_aidx[r0];
        int a1 = sh_aidx[r1];
        float w0 = GELU_EPI ? 1.0f : sh_wt[r0];
        float w1 = GELU_EPI ? 1.0f : sh_wt[r1];
        #pragma unroll
        for (int nf = 0; nf < 4; nf++) {
            int cidx = nbase + nf * 8 + (l & 3) * 2;
            float b0c = sh_bias[cidx], b1c = sh_bias[cidx + 1];
            if (a0 >= 0) {
                float v0 = acc[mf][nf][0] + b0c;
                float v1 = acc[mf][nf][1] + b1c;
                if (GELU_EPI) {
                    __half2 hv = __floats2half2_rn(gelu_exact(v0), gelu_exact(v1));
                    *(__half2*)(g_H + (size_t)a0 * NOUT + n0 + cidx) = hv;
                } else {
                    *(float2*)(g_Y + (size_t)a0 * NOUT + n0 + cidx) =
                        make_float2(v0 * w0, v1 * w0);
                }
            }
            if (a1 >= 0) {
                float v2 = acc[mf][nf][2] + b0c;
                float v3 = acc[mf][nf][3] + b1c;
                if (GELU_EPI) {
                    __half2 hv = __floats2half2_rn(gelu_exact(v2), gelu_exact(v3));
                    *(__half2*)(g_H + (size_t)a1 * NOUT + n0 + cidx) = hv;
                } else {
                    *(float2*)(g_Y + (size_t)a1 * NOUT + n0 + cidx) =
                        make_float2(v2 * w1, v3 * w1);
                }
            }
        }
    }
}

// ---------------- combine ----------------
__global__ void combine_kernel(float* __restrict__ out, int N) {
    int i = blockIdx.x * blockDim.x + threadIdx.x;
    int total = N * (D_DIM / 4);
    if (i >= total) return;
    int n = i / (D_DIM / 4);
    int c = i - n * (D_DIM / 4);
    const float4* Y = (const float4*)g_Y;
    float4 a = Y[(size_t)(2 * n) * (D_DIM / 4) + c];
    float4 b = Y[(size_t)(2 * n + 1) * (D_DIM / 4) + c];
    ((float4*)out)[i] = make_float4(a.x + b.x, a.y + b.y, a.z + b.z, a.w + b.w);
}

// ---------------- launch ----------------
extern "C" void kernel_launch(void* const* d_in, const int* in_sizes, int n_in,
                              void* d_out, int out_size) {
    const float* x  = (const float*)d_in[0];
    const float* Wg = (const float*)d_in[1];
    const float* W1 = (const float*)d_in[2];
    const float* b1 = (const float*)d_in[3];
    const float* W2 = (const float*)d_in[4];
    const float* b2 = (const float*)d_in[5];
    float* out = (float*)d_out;
    int N = in_sizes[0] / D_DIM;   // 8192

    cudaFuncSetAttribute(moe_mma_kernel<D_DIM, H_DIM, true>,
                         cudaFuncAttributeMaxDynamicSharedMemorySize, SMEM_DYN);
    cudaFuncSetAttribute(moe_mma_kernel<H_DIM, D_DIM, false>,
                         cudaFuncAttributeMaxDynamicSharedMemorySize, SMEM_DYN);

    __half* w1c; cudaGetSymbolAddress((void**)&w1c, g_W1c);
    __half* w2c; cudaGetSymbolAddress((void**)&w2c, g_W2c);
    __half* xc;  cudaGetSymbolAddress((void**)&xc,  g_Xc);
    __half* hbuf; cudaGetSymbolAddress((void**)&hbuf, g_H);

    int wn4 = (E_NUM * H_DIM * D_DIM) / 4;
    int xn4 = (N * D_DIM) / 4;
    cvt_f16_kernel<<<(wn4 + 255) / 256, 256>>>((const float4*)W1, (__half2*)w1c, wn4);
    cvt_f16_kernel<<<(wn4 + 255) / 256, 256>>>((const float4*)W2, (__half2*)w2c, wn4);
    cvt_f16_kernel<<<(xn4 + 255) / 256, 256>>>((const float4*)x,  (__half2*)xc,  xn4);

    zero_kernel<<<1, 32>>>();
    gate_kernel<<<(N + 7) / 8, 256>>>(x, Wg, N);
    moe_mma_kernel<D_DIM, H_DIM, true >
        <<<dim3(H_DIM / BN, MAXA / BM, E_NUM), 256, SMEM_DYN>>>(xc, w1c, b1);
    moe_mma_kernel<H_DIM, D_DIM, false>
        <<<dim3(D_DIM / BN, MAXA / BM, E_NUM), 256, SMEM_DYN>>>(hbuf, w2c, b2);
    combine_kernel<<<(N * (D_DIM / 4) + 255) / 256, 256>>>(out, N);
}